// round 10
// baseline (speedup 1.0000x reference)
#include <cuda_runtime.h>
#include <cuda_bf16.h>
#include <mma.h>
#include <cstdint>

using namespace nvcuda;

// GCNAggregator 3-kernel pipeline:
//   K0: W -> bf16 hi/lo (once)
//   K1: mean[row] = mean_s features[sample[row][s]] -> bf16 hi/lo
//   K2: out = relu( A @ W ) via 3-term bf16-split WMMA, all operands global.

#define D_DIM 128
#define S_SAMPLES 25
#define N_NODES 100000
#define N_ROWS 32768

// __device__ scratch (allowed; no runtime allocation)
__device__ __nv_bfloat16 g_Whi[D_DIM * D_DIM];
__device__ __nv_bfloat16 g_Wlo[D_DIM * D_DIM];
__device__ __nv_bfloat16 g_Ahi[N_ROWS * D_DIM];
__device__ __nv_bfloat16 g_Alo[N_ROWS * D_DIM];

// ---------------- K0: W split (64 blocks x 256 thr, 1 elem each) ----------------
__global__ void wsplit_kernel(const float* __restrict__ W)
{
    const int i = blockIdx.x * 256 + threadIdx.x;   // 0..16383
    const float v = W[i];
    const __nv_bfloat16 h = __float2bfloat16(v);
    g_Whi[i] = h;
    g_Wlo[i] = __float2bfloat16(v - __bfloat162float(h));
}

// ---------------- K1: gather + mean -> bf16 hi/lo ----------------
#define K1_THREADS 256
#define K1_WARPS 8
#define K1_GRID 1024          // 1024*8 warps * 4 rows = 32768 rows

__global__ __launch_bounds__(K1_THREADS)
void gather_mean_kernel(const float* __restrict__ features,
                        const int* __restrict__ sample)
{
    const int wid  = threadIdx.x >> 5;
    const int lane = threadIdx.x & 31;
    const int k0   = lane * 4;
    const int wglobal = blockIdx.x * K1_WARPS + wid;   // 0..8191

    #pragma unroll
    for (int r = 0; r < 4; r++) {
        const int row = wglobal + r * (K1_GRID * K1_WARPS);
        const int* idxp = sample + (long long)row * S_SAMPLES;

        float4 acc = make_float4(0.f, 0.f, 0.f, 0.f);
        #pragma unroll
        for (int s = 0; s < S_SAMPLES; s++) {
            int node = __ldg(&idxp[s]);                 // uniform broadcast
            node = min(max(node, 0), N_NODES - 1);      // defensive clamp
            const float4 v = *reinterpret_cast<const float4*>(
                &features[(long long)node * D_DIM + k0]);
            acc.x += v.x; acc.y += v.y; acc.z += v.z; acc.w += v.w;
        }
        const float inv = 1.0f / (float)S_SAMPLES;
        acc.x *= inv; acc.y *= inv; acc.z *= inv; acc.w *= inv;

        const __nv_bfloat16 hx = __float2bfloat16(acc.x);
        const __nv_bfloat16 hy = __float2bfloat16(acc.y);
        const __nv_bfloat16 hz = __float2bfloat16(acc.z);
        const __nv_bfloat16 hw = __float2bfloat16(acc.w);

        __nv_bfloat162 hi0(hx, hy), hi1(hz, hw);
        __nv_bfloat162 lo0(__float2bfloat16(acc.x - __bfloat162float(hx)),
                           __float2bfloat16(acc.y - __bfloat162float(hy)));
        __nv_bfloat162 lo1(__float2bfloat16(acc.z - __bfloat162float(hz)),
                           __float2bfloat16(acc.w - __bfloat162float(hw)));

        const long long e = (long long)row * D_DIM + k0;   // 8B-aligned (x2)
        *reinterpret_cast<__nv_bfloat162*>(&g_Ahi[e])     = hi0;
        *reinterpret_cast<__nv_bfloat162*>(&g_Ahi[e + 2]) = hi1;
        *reinterpret_cast<__nv_bfloat162*>(&g_Alo[e])     = lo0;
        *reinterpret_cast<__nv_bfloat162*>(&g_Alo[e + 2]) = lo1;
    }
}

// ---------------- K2: WMMA GEMM + relu, no smem ----------------
#define K2_THREADS 256
#define K2_ROWS 64

__global__ __launch_bounds__(K2_THREADS)
void gemm_relu_kernel(float* __restrict__ out)
{
    const int wid  = threadIdx.x >> 5;      // 0..7
    const int row0 = blockIdx.x * K2_ROWS;
    const int wr = row0 + (wid >> 2) * 32;  // global row base of this warp
    const int wc = (wid & 3) * 32;          // col base: 0,32,64,96

    wmma::fragment<wmma::accumulator, 16, 16, 16, float> acc[2][2];
    #pragma unroll
    for (int i = 0; i < 2; i++)
        #pragma unroll
        for (int j = 0; j < 2; j++)
            wmma::fill_fragment(acc[i][j], 0.0f);

    #pragma unroll
    for (int ks = 0; ks < D_DIM / 16; ks++) {
        wmma::fragment<wmma::matrix_a, 16, 16, 16, __nv_bfloat16,
                       wmma::row_major> aHi[2], aLo[2];
        wmma::fragment<wmma::matrix_b, 16, 16, 16, __nv_bfloat16,
                       wmma::row_major> bHi[2], bLo[2];

        #pragma unroll
        for (int i = 0; i < 2; i++) {
            const long long e = (long long)(wr + i * 16) * D_DIM + ks * 16;
            wmma::load_matrix_sync(aHi[i], &g_Ahi[e], D_DIM);
            wmma::load_matrix_sync(aLo[i], &g_Alo[e], D_DIM);
        }
        #pragma unroll
        for (int j = 0; j < 2; j++) {
            const int e = (ks * 16) * D_DIM + wc + j * 16;
            wmma::load_matrix_sync(bHi[j], &g_Whi[e], D_DIM);
            wmma::load_matrix_sync(bLo[j], &g_Wlo[e], D_DIM);
        }

        #pragma unroll
        for (int i = 0; i < 2; i++)
            #pragma unroll
            for (int j = 0; j < 2; j++) {
                wmma::mma_sync(acc[i][j], aHi[i], bHi[j], acc[i][j]);
                wmma::mma_sync(acc[i][j], aHi[i], bLo[j], acc[i][j]);
                wmma::mma_sync(acc[i][j], aLo[i], bHi[j], acc[i][j]);
            }
    }

    #pragma unroll
    for (int i = 0; i < 2; i++)
        #pragma unroll
        for (int j = 0; j < 2; j++) {
            #pragma unroll
            for (int t = 0; t < acc[i][j].num_elements; t++)
                acc[i][j].x[t] = fmaxf(acc[i][j].x[t], 0.0f);
            wmma::store_matrix_sync(
                &out[(long long)(wr + i * 16) * D_DIM + wc + j * 16],
                acc[i][j], D_DIM, wmma::mem_row_major);
        }
}

extern "C" void kernel_launch(void* const* d_in, const int* in_sizes, int n_in,
                              void* d_out, int out_size)
{
    // Identify inputs by element count — robust to d_in ordering.
    int imax = 0, imin = 0;
    for (int i = 1; i < 3 && i < n_in; i++) {
        if (in_sizes[i] > in_sizes[imax]) imax = i;
        if (in_sizes[i] < in_sizes[imin]) imin = i;
    }
    const int imid = 3 - imax - imin;

    const float* features = (const float*)d_in[imax];
    const float* W        = (const float*)d_in[imin];
    const int*   sample   = (const int*)d_in[imid];

    float* out = (float*)d_out;

    const int n_rows = in_sizes[imid] / S_SAMPLES;   // 32768
    const int grid2  = n_rows / K2_ROWS;             // 512

    wsplit_kernel<<<64, 256>>>(W);
    gather_mean_kernel<<<K1_GRID, K1_THREADS>>>(features, sample);
    gemm_relu_kernel<<<grid2, K2_THREADS>>>(out);
}

// round 11
// speedup vs baseline: 1.4375x; 1.4375x over previous
#include <cuda_runtime.h>
#include <cuda_bf16.h>
#include <mma.h>
#include <cstdint>

using namespace nvcuda;

// GCNAggregator 2-kernel pipeline:
//   K1: mean[row] = mean_s features[sample[row][s]] -> g_Ahi/g_Alo (bf16 split)
//       (first 16 blocks also split W -> g_Whi/g_Wlo)
//   K2: out = relu( A @ W ): stage bf16 tiles into smem (pure copy, no math),
//       LDSM + 3-term bf16-split WMMA, relu, store.

#define D_DIM 128
#define S_SAMPLES 25
#define N_NODES 100000
#define N_ROWS 32768

__device__ __nv_bfloat16 g_Whi[D_DIM * D_DIM];
__device__ __nv_bfloat16 g_Wlo[D_DIM * D_DIM];
__device__ __nv_bfloat16 g_Ahi[N_ROWS * D_DIM];
__device__ __nv_bfloat16 g_Alo[N_ROWS * D_DIM];

// ---------------- K1: gather + mean -> bf16 hi/lo (+ W split) ----------------
#define K1_THREADS 256
#define K1_WARPS 8
#define K1_GRID 1024          // 1024*8 warps * 4 rows = 32768 rows

__global__ __launch_bounds__(K1_THREADS)
void gather_mean_kernel(const float* __restrict__ features,
                        const int* __restrict__ sample,
                        const float* __restrict__ W)
{
    // First 16 blocks also split W (4096 threads x 1 float4 = 16384 elems).
    if (blockIdx.x < 16) {
        const int e = (blockIdx.x * K1_THREADS + threadIdx.x) * 4;
        const float4 v = *reinterpret_cast<const float4*>(&W[e]);
        const __nv_bfloat16 hx = __float2bfloat16(v.x);
        const __nv_bfloat16 hy = __float2bfloat16(v.y);
        const __nv_bfloat16 hz = __float2bfloat16(v.z);
        const __nv_bfloat16 hw = __float2bfloat16(v.w);
        *reinterpret_cast<__nv_bfloat162*>(&g_Whi[e])     = __nv_bfloat162(hx, hy);
        *reinterpret_cast<__nv_bfloat162*>(&g_Whi[e + 2]) = __nv_bfloat162(hz, hw);
        *reinterpret_cast<__nv_bfloat162*>(&g_Wlo[e]) =
            __nv_bfloat162(__float2bfloat16(v.x - __bfloat162float(hx)),
                           __float2bfloat16(v.y - __bfloat162float(hy)));
        *reinterpret_cast<__nv_bfloat162*>(&g_Wlo[e + 2]) =
            __nv_bfloat162(__float2bfloat16(v.z - __bfloat162float(hz)),
                           __float2bfloat16(v.w - __bfloat162float(hw)));
    }

    const int wid  = threadIdx.x >> 5;
    const int lane = threadIdx.x & 31;
    const int k0   = lane * 4;
    const int wglobal = blockIdx.x * K1_WARPS + wid;   // 0..8191

    #pragma unroll
    for (int r = 0; r < 4; r++) {
        const int row = wglobal + r * (K1_GRID * K1_WARPS);
        const int* idxp = sample + (long long)row * S_SAMPLES;

        float4 acc = make_float4(0.f, 0.f, 0.f, 0.f);
        #pragma unroll
        for (int s = 0; s < S_SAMPLES; s++) {
            int node = __ldg(&idxp[s]);                 // uniform broadcast
            node = min(max(node, 0), N_NODES - 1);      // defensive clamp
            const float4 v = *reinterpret_cast<const float4*>(
                &features[(long long)node * D_DIM + k0]);
            acc.x += v.x; acc.y += v.y; acc.z += v.z; acc.w += v.w;
        }
        const float inv = 1.0f / (float)S_SAMPLES;
        acc.x *= inv; acc.y *= inv; acc.z *= inv; acc.w *= inv;

        const __nv_bfloat16 hx = __float2bfloat16(acc.x);
        const __nv_bfloat16 hy = __float2bfloat16(acc.y);
        const __nv_bfloat16 hz = __float2bfloat16(acc.z);
        const __nv_bfloat16 hw = __float2bfloat16(acc.w);

        const long long e = (long long)row * D_DIM + k0;   // 8B-aligned
        *reinterpret_cast<__nv_bfloat162*>(&g_Ahi[e])     = __nv_bfloat162(hx, hy);
        *reinterpret_cast<__nv_bfloat162*>(&g_Ahi[e + 2]) = __nv_bfloat162(hz, hw);
        *reinterpret_cast<__nv_bfloat162*>(&g_Alo[e]) =
            __nv_bfloat162(__float2bfloat16(acc.x - __bfloat162float(hx)),
                           __float2bfloat16(acc.y - __bfloat162float(hy)));
        *reinterpret_cast<__nv_bfloat162*>(&g_Alo[e + 2]) =
            __nv_bfloat162(__float2bfloat16(acc.z - __bfloat162float(hz)),
                           __float2bfloat16(acc.w - __bfloat162float(hw)));
    }
}

// ---------------- K2: WMMA GEMM + relu (smem-staged bf16, no converts) -------
#define K2_THREADS 256
#define K2_ROWS 64
#define LDS_A 136                      // bf16 stride, 272B rows -> conflict-free
#define SA_ELEMS (K2_ROWS * LDS_A)     // 8704
#define SW_ELEMS (D_DIM * LDS_A)       // 17408

__global__ __launch_bounds__(K2_THREADS, 2)
void gemm_relu_kernel(float* __restrict__ out)
{
    extern __shared__ __nv_bfloat16 smem[];
    __nv_bfloat16* sAhi = smem;                    // [64][136]
    __nv_bfloat16* sAlo = sAhi + SA_ELEMS;
    __nv_bfloat16* sWhi = sAlo + SA_ELEMS;         // [128][136]
    __nv_bfloat16* sWlo = sWhi + SW_ELEMS;

    const int tid  = threadIdx.x;
    const int wid  = tid >> 5;
    const int row0 = blockIdx.x * K2_ROWS;

    // ---- Stage W hi/lo: pure uint4 copies (128 rows x 16 uint4 each) ----
    #pragma unroll
    for (int i = 0; i < 8; i++) {
        const int idx = tid + i * K2_THREADS;   // 0..2047
        const int r   = idx >> 4;               // 0..127
        const int c   = (idx & 15) * 8;         // bf16 col, 8 per uint4
        *reinterpret_cast<uint4*>(&sWhi[r * LDS_A + c]) =
            *reinterpret_cast<const uint4*>(&g_Whi[r * D_DIM + c]);
        *reinterpret_cast<uint4*>(&sWlo[r * LDS_A + c]) =
            *reinterpret_cast<const uint4*>(&g_Wlo[r * D_DIM + c]);
    }
    // ---- Stage A hi/lo: 64 rows x 16 uint4 each ----
    #pragma unroll
    for (int i = 0; i < 4; i++) {
        const int idx = tid + i * K2_THREADS;   // 0..1023
        const int r   = idx >> 4;               // 0..63
        const int c   = (idx & 15) * 8;
        const long long e = (long long)(row0 + r) * D_DIM + c;
        *reinterpret_cast<uint4*>(&sAhi[r * LDS_A + c]) =
            *reinterpret_cast<const uint4*>(&g_Ahi[e]);
        *reinterpret_cast<uint4*>(&sAlo[r * LDS_A + c]) =
            *reinterpret_cast<const uint4*>(&g_Alo[e]);
    }
    __syncthreads();

    // ---- WMMA GEMM [64,128] x [128,128], 3-term bf16 split ----
    const int wr = (wid >> 2) * 32;   // 0 or 32
    const int wc = (wid & 3) * 32;    // 0,32,64,96

    wmma::fragment<wmma::accumulator, 16, 16, 16, float> acc[2][2];
    #pragma unroll
    for (int i = 0; i < 2; i++)
        #pragma unroll
        for (int j = 0; j < 2; j++)
            wmma::fill_fragment(acc[i][j], 0.0f);

    #pragma unroll
    for (int ks = 0; ks < D_DIM / 16; ks++) {
        wmma::fragment<wmma::matrix_a, 16, 16, 16, __nv_bfloat16,
                       wmma::row_major> aHi[2], aLo[2];
        wmma::fragment<wmma::matrix_b, 16, 16, 16, __nv_bfloat16,
                       wmma::row_major> bHi[2], bLo[2];

        #pragma unroll
        for (int i = 0; i < 2; i++) {
            const __nv_bfloat16* pa = &sAhi[(wr + i * 16) * LDS_A + ks * 16];
            wmma::load_matrix_sync(aHi[i], pa, LDS_A);
            wmma::load_matrix_sync(aLo[i], pa + SA_ELEMS, LDS_A);   // sAlo
        }
        #pragma unroll
        for (int j = 0; j < 2; j++) {
            const __nv_bfloat16* pb = &sWhi[(ks * 16) * LDS_A + wc + j * 16];
            wmma::load_matrix_sync(bHi[j], pb, LDS_A);
            wmma::load_matrix_sync(bLo[j], pb + SW_ELEMS, LDS_A);   // sWlo
        }

        #pragma unroll
        for (int i = 0; i < 2; i++)
            #pragma unroll
            for (int j = 0; j < 2; j++) {
                wmma::mma_sync(acc[i][j], aHi[i], bHi[j], acc[i][j]);
                wmma::mma_sync(acc[i][j], aHi[i], bLo[j], acc[i][j]);
                wmma::mma_sync(acc[i][j], aLo[i], bHi[j], acc[i][j]);
            }
    }

    // ---- Epilogue: relu + store ----
    #pragma unroll
    for (int i = 0; i < 2; i++)
        #pragma unroll
        for (int j = 0; j < 2; j++) {
            #pragma unroll
            for (int t = 0; t < acc[i][j].num_elements; t++)
                acc[i][j].x[t] = fmaxf(acc[i][j].x[t], 0.0f);
            wmma::store_matrix_sync(
                &out[(long long)(row0 + wr + i * 16) * D_DIM + wc + j * 16],
                acc[i][j], D_DIM, wmma::mem_row_major);
        }
}

extern "C" void kernel_launch(void* const* d_in, const int* in_sizes, int n_in,
                              void* d_out, int out_size)
{
    // Identify inputs by element count — robust to d_in ordering.
    int imax = 0, imin = 0;
    for (int i = 1; i < 3 && i < n_in; i++) {
        if (in_sizes[i] > in_sizes[imax]) imax = i;
        if (in_sizes[i] < in_sizes[imin]) imin = i;
    }
    const int imid = 3 - imax - imin;

    const float* features = (const float*)d_in[imax];
    const float* W        = (const float*)d_in[imin];
    const int*   sample   = (const int*)d_in[imid];

    float* out = (float*)d_out;

    const int n_rows = in_sizes[imid] / S_SAMPLES;   // 32768
    const int grid2  = n_rows / K2_ROWS;             // 512

    const int smem_bytes = (2 * SA_ELEMS + 2 * SW_ELEMS) * sizeof(__nv_bfloat16);

    cudaFuncSetAttribute(gemm_relu_kernel,
                         cudaFuncAttributeMaxDynamicSharedMemorySize,
                         smem_bytes);

    gather_mean_kernel<<<K1_GRID, K1_THREADS>>>(features, sample, W);
    gemm_relu_kernel<<<grid2, K2_THREADS, smem_bytes>>>(out);
}

// round 12
// speedup vs baseline: 1.4960x; 1.0407x over previous
#include <cuda_runtime.h>
#include <cuda_bf16.h>
#include <mma.h>
#include <cstdint>

using namespace nvcuda;

// GCNAggregator 2-kernel pipeline:
//   K1: mean[row] = mean_s features[sample[row][s]] -> d_out (fp32)
//   K2: persistent-tile bf16-split WMMA GEMM + relu, in-place on d_out.
//       W staged once per CTA; A tiles software-pipelined (reg prefetch).

#define D_DIM 128
#define S_SAMPLES 25
#define N_NODES 100000

// ---------------- K1: gather + mean ----------------
#define K1_THREADS 256
#define K1_WARPS 8
#define K1_GRID 1024          // 1024*8 warps * 4 rows = 32768 rows

__global__ __launch_bounds__(K1_THREADS)
void gather_mean_kernel(const float* __restrict__ features,
                        const int* __restrict__ sample,
                        float* __restrict__ mean_out)
{
    const int wid  = threadIdx.x >> 5;
    const int lane = threadIdx.x & 31;
    const int k0   = lane * 4;
    const int wglobal = blockIdx.x * K1_WARPS + wid;   // 0..8191

    #pragma unroll
    for (int r = 0; r < 4; r++) {
        const int row = wglobal + r * (K1_GRID * K1_WARPS);
        const int* idxp = sample + (long long)row * S_SAMPLES;

        float4 acc = make_float4(0.f, 0.f, 0.f, 0.f);
        #pragma unroll
        for (int s = 0; s < S_SAMPLES; s++) {
            int node = __ldg(&idxp[s]);                 // uniform broadcast
            node = min(max(node, 0), N_NODES - 1);      // defensive clamp
            const float4 v = *reinterpret_cast<const float4*>(
                &features[(long long)node * D_DIM + k0]);
            acc.x += v.x; acc.y += v.y; acc.z += v.z; acc.w += v.w;
        }
        const float inv = 1.0f / (float)S_SAMPLES;
        acc.x *= inv; acc.y *= inv; acc.z *= inv; acc.w *= inv;
        *reinterpret_cast<float4*>(&mean_out[(long long)row * D_DIM + k0]) = acc;
    }
}

// ---------------- K2: persistent-tile WMMA GEMM + relu ----------------
#define K2_THREADS 256
#define K2_GRID 256
#define TILE_ROWS 32
#define TILES_PER_CTA 4          // 256 * 4 * 32 = 32768 rows
#define LDS_A 136                // bf16 stride, 272B rows
#define SA_ELEMS (TILE_ROWS * LDS_A)   // 4352
#define SW_ELEMS (D_DIM * LDS_A)       // 17408

__global__ __launch_bounds__(K2_THREADS, 2)
void gemm_relu_kernel(const float* __restrict__ W,
                      float* __restrict__ inout)   // means in, relu out
{
    extern __shared__ __nv_bfloat16 smem[];
    __nv_bfloat16* sAhi = smem;                    // [32][136]
    __nv_bfloat16* sAlo = sAhi + SA_ELEMS;
    __nv_bfloat16* sWhi = sAlo + SA_ELEMS;         // [128][136]
    __nv_bfloat16* sWlo = sWhi + SW_ELEMS;

    const int tid  = threadIdx.x;
    const int wid  = tid >> 5;
    const long long ctaRow0 = (long long)blockIdx.x * (TILES_PER_CTA * TILE_ROWS);

    // ---- Stage W once: fp32 -> bf16 hi/lo ----
    #pragma unroll
    for (int i = 0; i < 16; i++) {
        const int idx = tid + i * K2_THREADS;     // 0..4095 float4
        const int k   = idx >> 5;
        const int n0  = (idx & 31) * 4;
        const float4 v = *reinterpret_cast<const float4*>(&W[k * D_DIM + n0]);
        const __nv_bfloat16 hx = __float2bfloat16(v.x);
        const __nv_bfloat16 hy = __float2bfloat16(v.y);
        const __nv_bfloat16 hz = __float2bfloat16(v.z);
        const __nv_bfloat16 hw = __float2bfloat16(v.w);
        *reinterpret_cast<__nv_bfloat162*>(&sWhi[k * LDS_A + n0]) =
            __nv_bfloat162(hx, hy);
        *reinterpret_cast<__nv_bfloat162*>(&sWhi[k * LDS_A + n0 + 2]) =
            __nv_bfloat162(hz, hw);
        *reinterpret_cast<__nv_bfloat162*>(&sWlo[k * LDS_A + n0]) =
            __nv_bfloat162(__float2bfloat16(v.x - __bfloat162float(hx)),
                           __float2bfloat16(v.y - __bfloat162float(hy)));
        *reinterpret_cast<__nv_bfloat162*>(&sWlo[k * LDS_A + n0 + 2]) =
            __nv_bfloat162(__float2bfloat16(v.z - __bfloat162float(hz)),
                           __float2bfloat16(v.w - __bfloat162float(hw)));
    }

    // Per-thread A-prefetch slice: 1024 float4 per tile / 256 thr = 4 float4.
    // idx = tid + i*256 -> row = idx>>5 (0..31), c4 = (idx&31)*4.
    float4 pf[4];
    #pragma unroll
    for (int i = 0; i < 4; i++) {
        const int idx = tid + i * K2_THREADS;
        pf[i] = *reinterpret_cast<const float4*>(
            &inout[(ctaRow0 + (idx >> 5)) * D_DIM + (idx & 31) * 4]);
    }

    const int wr = (wid >> 2) * 16;   // 0 or 16
    const int wc = (wid & 3) * 32;    // 0,32,64,96

    for (int t = 0; t < TILES_PER_CTA; t++) {
        const long long tileRow0 = ctaRow0 + (long long)t * TILE_ROWS;

        // ---- STS current tile (convert fp32 -> bf16 hi/lo) ----
        #pragma unroll
        for (int i = 0; i < 4; i++) {
            const int idx = tid + i * K2_THREADS;
            const int r   = idx >> 5;
            const int c0  = (idx & 31) * 4;
            const float4 v = pf[i];
            const __nv_bfloat16 hx = __float2bfloat16(v.x);
            const __nv_bfloat16 hy = __float2bfloat16(v.y);
            const __nv_bfloat16 hz = __float2bfloat16(v.z);
            const __nv_bfloat16 hw = __float2bfloat16(v.w);
            *reinterpret_cast<__nv_bfloat162*>(&sAhi[r * LDS_A + c0]) =
                __nv_bfloat162(hx, hy);
            *reinterpret_cast<__nv_bfloat162*>(&sAhi[r * LDS_A + c0 + 2]) =
                __nv_bfloat162(hz, hw);
            *reinterpret_cast<__nv_bfloat162*>(&sAlo[r * LDS_A + c0]) =
                __nv_bfloat162(__float2bfloat16(v.x - __bfloat162float(hx)),
                               __float2bfloat16(v.y - __bfloat162float(hy)));
            *reinterpret_cast<__nv_bfloat162*>(&sAlo[r * LDS_A + c0 + 2]) =
                __nv_bfloat162(__float2bfloat16(v.z - __bfloat162float(hz)),
                               __float2bfloat16(v.w - __bfloat162float(hw)));
        }
        __syncthreads();

        // ---- Prefetch next tile (LDG issues now, waits later) ----
        if (t + 1 < TILES_PER_CTA) {
            const long long nRow0 = tileRow0 + TILE_ROWS;
            #pragma unroll
            for (int i = 0; i < 4; i++) {
                const int idx = tid + i * K2_THREADS;
                pf[i] = *reinterpret_cast<const float4*>(
                    &inout[(nRow0 + (idx >> 5)) * D_DIM + (idx & 31) * 4]);
            }
        }

        // ---- WMMA: [32,128] x [128,128], 3-term bf16 split ----
        wmma::fragment<wmma::accumulator, 16, 16, 16, float> acc[2];
        wmma::fill_fragment(acc[0], 0.0f);
        wmma::fill_fragment(acc[1], 0.0f);

        #pragma unroll
        for (int ks = 0; ks < D_DIM / 16; ks++) {
            wmma::fragment<wmma::matrix_a, 16, 16, 16, __nv_bfloat16,
                           wmma::row_major> aHi, aLo;
            wmma::fragment<wmma::matrix_b, 16, 16, 16, __nv_bfloat16,
                           wmma::row_major> bHi[2], bLo[2];

            const __nv_bfloat16* pa = &sAhi[wr * LDS_A + ks * 16];
            wmma::load_matrix_sync(aHi, pa, LDS_A);
            wmma::load_matrix_sync(aLo, pa + SA_ELEMS, LDS_A);     // sAlo

            #pragma unroll
            for (int j = 0; j < 2; j++) {
                const __nv_bfloat16* pb =
                    &sWhi[(ks * 16) * LDS_A + wc + j * 16];
                wmma::load_matrix_sync(bHi[j], pb, LDS_A);
                wmma::load_matrix_sync(bLo[j], pb + SW_ELEMS, LDS_A); // sWlo
            }

            #pragma unroll
            for (int j = 0; j < 2; j++) {
                wmma::mma_sync(acc[j], aHi, bHi[j], acc[j]);
                wmma::mma_sync(acc[j], aHi, bLo[j], acc[j]);
                wmma::mma_sync(acc[j], aLo, bHi[j], acc[j]);
            }
        }

        // ---- Epilogue: relu + store ----
        #pragma unroll
        for (int j = 0; j < 2; j++) {
            #pragma unroll
            for (int e = 0; e < acc[j].num_elements; e++)
                acc[j].x[e] = fmaxf(acc[j].x[e], 0.0f);
            wmma::store_matrix_sync(
                &inout[(tileRow0 + wr) * D_DIM + wc + j * 16],
                acc[j], D_DIM, wmma::mem_row_major);
        }
        __syncthreads();   // protect sA before next STS
    }
}

extern "C" void kernel_launch(void* const* d_in, const int* in_sizes, int n_in,
                              void* d_out, int out_size)
{
    // Identify inputs by element count — robust to d_in ordering.
    int imax = 0, imin = 0;
    for (int i = 1; i < 3 && i < n_in; i++) {
        if (in_sizes[i] > in_sizes[imax]) imax = i;
        if (in_sizes[i] < in_sizes[imin]) imin = i;
    }
    const int imid = 3 - imax - imin;

    const float* features = (const float*)d_in[imax];
    const float* W        = (const float*)d_in[imin];
    const int*   sample   = (const int*)d_in[imid];

    float* out = (float*)d_out;

    const int smem_bytes = (2 * SA_ELEMS + 2 * SW_ELEMS) * sizeof(__nv_bfloat16);
    // = (2*4352 + 2*17408) * 2 = 87,040 B

    cudaFuncSetAttribute(gemm_relu_kernel,
                         cudaFuncAttributeMaxDynamicSharedMemorySize,
                         smem_bytes);

    gather_mean_kernel<<<K1_GRID, K1_THREADS>>>(features, sample, out);
    gemm_relu_kernel<<<K2_GRID, K2_THREADS, smem_bytes>>>(W, out);
}